// round 17
// baseline (speedup 1.0000x reference)
#include <cuda_runtime.h>
#include <cuda_bf16.h>
#include <cuda_fp16.h>
#include <cstdint>
#include <cstddef>

// Problem constants
#define BB   16
#define CC   64
#define NN   2048
#define KK   20
#define OUTC 64

// ---------------- scratch (no allocations allowed) ----------------
__device__ __align__(16) float g_xt[BB * NN * CC];     // x transposed: [b][n][c]
__device__ float g_sq[BB * NN];                        // squared norms (bit-exact vs ref)
__device__ int   g_idx[BB * NN * KK];                  // knn indices, ascending dist
__device__ int   g_cand[BB * NN * 32];                 // approx top-32 candidates
__device__ float g_scale[OUTC];
__device__ float g_shift[OUTC];
__device__ float g_bps[OUTC * 32];                     // bn partial sums
__device__ float g_bpss[OUTC * 32];                    // bn partial sumsq
__device__ __align__(16) __half g_dh[(size_t)BB * NN * NN];   // approx distance (fp16, 128MB)
// split-bf16 operands for tensor-core kernels
__device__ __align__(16) __nv_bfloat16 g_xhi[BB * NN * CC];   // [b][n][c]
__device__ __align__(16) __nv_bfloat16 g_xlo[BB * NN * CC];
__device__ __align__(16) __nv_bfloat16 g_wbh[21 * OUTC * CC]; // [slot][o][c]
__device__ __align__(16) __nv_bfloat16 g_wbl[21 * OUTC * CC];

__device__ __forceinline__ void mma16816(float* c, uint32_t a0, uint32_t a1,
                                         uint32_t a2, uint32_t a3,
                                         uint32_t b0, uint32_t b1) {
    asm volatile(
        "mma.sync.aligned.m16n8k16.row.col.f32.bf16.bf16.f32 "
        "{%0,%1,%2,%3}, {%4,%5,%6,%7}, {%8,%9}, {%0,%1,%2,%3};"
        : "+f"(c[0]), "+f"(c[1]), "+f"(c[2]), "+f"(c[3])
        : "r"(a0), "r"(a1), "r"(a2), "r"(a3), "r"(b0), "r"(b1));
}

// monotonic float->uint map (strictly order-preserving incl. negatives)
__device__ __forceinline__ unsigned mono_f(float f) {
    unsigned u = __float_as_uint(f);
    return u ^ (((unsigned)((int)u >> 31)) | 0x80000000u);
}

// ---------------- prep: transpose x -> xt (+ bf16 hi/lo split) ----------------
__global__ void prep_xt_kernel(const float* __restrict__ x) {
    __shared__ float sm[64][129];
    int b = blockIdx.y, n0 = blockIdx.x * 128, t = threadIdx.x;
    const float* xb = x + (size_t)b * CC * NN;
#pragma unroll
    for (int c = 0; c < 64; c++)
        sm[c][t] = xb[(size_t)c * NN + n0 + t];
    __syncthreads();
    float* xtb = g_xt + ((size_t)b * NN + n0) * 64;
    __nv_bfloat16* xh = g_xhi + ((size_t)b * NN + n0) * 64;
    __nv_bfloat16* xl = g_xlo + ((size_t)b * NN + n0) * 64;
#pragma unroll 4
    for (int i = 0; i < 64; i++) {
        int flat = i * 128 + t;
        int c = flat & 63, p = flat >> 6;
        float v = sm[c][p];
        xtb[(size_t)p * 64 + c] = v;
        __nv_bfloat16 h = __float2bfloat16(v);
        xh[(size_t)p * 64 + c] = h;
        xl[(size_t)p * 64 + c] = __float2bfloat16(v - __bfloat162float(h));
    }
}

// ---------------- sq: XLA:CPU + LLVM LoopVectorizer replica ----------------
// VF=4 (NEON), IC=2 -> 8 mod-8 lanes; verified bit-exact in round 7.
__global__ __launch_bounds__(256) void sq_kernel() {
    int p = blockIdx.x * 256 + threadIdx.x;
    const float4* z = (const float4*)(g_xt + (size_t)p * 64);
    float a[8];
#pragma unroll
    for (int l = 0; l < 8; l++) a[l] = 0.f;
#pragma unroll
    for (int i = 0; i < 8; i++) {
        float4 v0 = z[2 * i];
        float4 v1 = z[2 * i + 1];
        a[0] = __fadd_rn(a[0], __fmul_rn(v0.x, v0.x));
        a[1] = __fadd_rn(a[1], __fmul_rn(v0.y, v0.y));
        a[2] = __fadd_rn(a[2], __fmul_rn(v0.z, v0.z));
        a[3] = __fadd_rn(a[3], __fmul_rn(v0.w, v0.w));
        a[4] = __fadd_rn(a[4], __fmul_rn(v1.x, v1.x));
        a[5] = __fadd_rn(a[5], __fmul_rn(v1.y, v1.y));
        a[6] = __fadd_rn(a[6], __fmul_rn(v1.z, v1.z));
        a[7] = __fadd_rn(a[7], __fmul_rn(v1.w, v1.w));
    }
    float t0 = __fadd_rn(a[0], a[4]);
    float t1 = __fadd_rn(a[1], a[5]);
    float t2 = __fadd_rn(a[2], a[6]);
    float t3 = __fadd_rn(a[3], a[7]);
    g_sq[p] = __fadd_rn(__fadd_rn(t0, t1), __fadd_rn(t2, t3));
}

// ---------------- prep: split weights -> bf16 hi/lo, [slot][o][c] ----------
__global__ void prep_wb_kernel(const float* __restrict__ w) {
    int slot = blockIdx.x;
    int e = blockIdx.y * 256 + threadIdx.x;   // 0..4095
    int o = e >> 6, c = e & 63;
    float val;
    if (slot == 0) {
        float s = 0.f;
        const float* w1 = w + ((size_t)o * 128 + c) * 20;
        const float* w2 = w + ((size_t)o * 128 + 64 + c) * 20;
#pragma unroll
        for (int j = 0; j < 20; j++) s += w1[j] - w2[j];
        val = s;
    } else {
        val = w[((size_t)o * 128 + 64 + c) * 20 + slot - 1];
    }
    __nv_bfloat16 h = __float2bfloat16(val);
    __nv_bfloat16 l = __float2bfloat16(val - __bfloat162float(h));
    g_wbh[slot * 4096 + o * 64 + c] = h;
    g_wbl[slot * 4096 + o * 64 + c] = l;
}

// ---------------- gram: approx distance matrix (plain bf16, single pass) ----
// CTA tile 128(i) x 128(j), 4 warps in a 2x2 layout, warp tile 64x64
// (4 m-tiles x 8 n-tiles, 128 fp32 acc regs). Per k-quarter each warp moves
// A 16 + B 16 LDS.32 for 32 MMAs -> 128 B/MMA (2.25x less crossbar traffic
// than the 16x128 warp tile). Per-output accumulation order is unchanged ->
// distances bitwise identical to round 16.
__global__ __launch_bounds__(128) void gram_kernel() {
    __shared__ __align__(16) __nv_bfloat16 ah[128 * 72];
    __shared__ __align__(16) __nv_bfloat16 bh[128 * 72];

    int tid = threadIdx.x, wid = tid >> 5, lane = tid & 31;
    int gid = lane >> 2, tig = lane & 3;
    int b = blockIdx.z;
    int i0 = blockIdx.y * 128, j0 = blockIdx.x * 128;
    const uint4* xh = (const uint4*)(g_xhi + (size_t)b * NN * 64);  // 8 uint4 per row

#pragma unroll
    for (int u = 0; u < 8; u++) {
        int e = tid + 128 * u;
        int r = e >> 3, ch = e & 7;
        *(uint4*)&ah[r * 72 + ch * 8] = xh[(size_t)(i0 + r) * 8 + ch];
        *(uint4*)&bh[r * 72 + ch * 8] = xh[(size_t)(j0 + r) * 8 + ch];
    }
    __syncthreads();

    int ib = (wid >> 1) * 64;   // warp i-offset within CTA tile
    int jb = (wid & 1) * 64;    // warp j-offset
    float acc[4][8][4];
#pragma unroll
    for (int mt = 0; mt < 4; mt++)
#pragma unroll
        for (int nb = 0; nb < 8; nb++)
#pragma unroll
            for (int k = 0; k < 4; k++) acc[mt][nb][k] = 0.f;

#pragma unroll
    for (int kk = 0; kk < 4; kk++) {
        int co = kk * 16 + tig * 2;
        uint32_t af[4][4];
#pragma unroll
        for (int mt = 0; mt < 4; mt++) {
            int row = ib + mt * 16 + gid;
            af[mt][0] = *(const uint32_t*)&ah[row * 72 + co];
            af[mt][1] = *(const uint32_t*)&ah[(row + 8) * 72 + co];
            af[mt][2] = *(const uint32_t*)&ah[row * 72 + co + 8];
            af[mt][3] = *(const uint32_t*)&ah[(row + 8) * 72 + co + 8];
        }
#pragma unroll
        for (int nb = 0; nb < 8; nb++) {
            uint32_t b0 = *(const uint32_t*)&bh[(jb + nb * 8 + gid) * 72 + co];
            uint32_t b1 = *(const uint32_t*)&bh[(jb + nb * 8 + gid) * 72 + co + 8];
#pragma unroll
            for (int mt = 0; mt < 4; mt++)
                mma16816(acc[mt][nb], af[mt][0], af[mt][1], af[mt][2], af[mt][3], b0, b1);
        }
    }

    __half* db = g_dh + (size_t)b * NN * NN;
#pragma unroll
    for (int mt = 0; mt < 4; mt++) {
        int r0 = i0 + ib + mt * 16 + gid;
        float si0 = g_sq[b * NN + r0];
        float si8 = g_sq[b * NN + r0 + 8];
#pragma unroll
        for (int nb = 0; nb < 8; nb++) {
            int jj = j0 + jb + nb * 8 + tig * 2;
            float sj0 = g_sq[b * NN + jj];
            float sj1 = g_sq[b * NN + jj + 1];
            float d00 = fmaxf(__fmaf_rn(-2.f, acc[mt][nb][0], __fadd_rn(si0, sj0)), 0.f);
            float d01 = fmaxf(__fmaf_rn(-2.f, acc[mt][nb][1], __fadd_rn(si0, sj1)), 0.f);
            float d80 = fmaxf(__fmaf_rn(-2.f, acc[mt][nb][2], __fadd_rn(si8, sj0)), 0.f);
            float d81 = fmaxf(__fmaf_rn(-2.f, acc[mt][nb][3], __fadd_rn(si8, sj1)), 0.f);
            *(__half2*)&db[(size_t)r0 * NN + jj]       = __floats2half2_rn(d00, d01);
            *(__half2*)&db[(size_t)(r0 + 8) * NN + jj] = __floats2half2_rn(d80, d81);
        }
    }
}

// ---------------- select: warp-cooperative approx top-32 ----------------
__global__ __launch_bounds__(256) void select_kernel() {
    int warp = threadIdx.x >> 5, lane = threadIdx.x & 31;
    int b = blockIdx.y;
    int q = blockIdx.x * 8 + warp;
    const __half2* row2 = (const __half2*)(g_dh + ((size_t)b * NN + q) * NN);

    unsigned lkey = 0xFFFFFFFFu;
    unsigned th = 0xFFFFFFFFu;

#pragma unroll 2
    for (int t = 0; t < 32; t++) {
        int j0 = t * 64 + lane * 2;
        __half2 hv = row2[t * 32 + lane];
        unsigned u0 = (unsigned)__half_as_ushort(__low2half(hv));
        unsigned u1 = (unsigned)__half_as_ushort(__high2half(hv));
        unsigned k0 = (u0 << 11) | (unsigned)j0;
        unsigned k1 = (u1 << 11) | (unsigned)(j0 + 1);
#pragma unroll
        for (int h = 0; h < 2; h++) {
            unsigned ck = h ? k1 : k0;
            int j = j0 + h;
            bool pass = (j != q) && (ck < th);
            unsigned bal = __ballot_sync(0xffffffffu, pass);
            while (bal) {
                int src = __ffs(bal) - 1;
                bal &= bal - 1;
                unsigned c2 = __shfl_sync(0xffffffffu, ck, src);
                if (c2 < th) {
                    unsigned up = __shfl_up_sync(0xffffffffu, lkey, 1);
                    if (lkey > c2)
                        lkey = (lane == 0 || up <= c2) ? c2 : up;
                    th = __shfl_sync(0xffffffffu, lkey, 31);
                }
            }
        }
    }
    g_cand[((size_t)b * NN + q) * 32 + lane] = (int)(lkey & 0x7FFu);
}

// ---------------- rescue: exact top-20 among 32 candidates ----------------
__global__ __launch_bounds__(128) void rescue_kernel() {
    __shared__ float rows[32][65];
    __shared__ float qrow[64];
    __shared__ float sqc[32];
    __shared__ int cidx[32];
    __shared__ float sqq_s;

    int tid = threadIdx.x;
    int b = blockIdx.y, q = blockIdx.x;
    const float* xb = g_xt + (size_t)b * NN * 64;

    if (tid < 32) {
        int c = g_cand[((size_t)b * NN + q) * 32 + tid];
        cidx[tid] = c;
        sqc[tid] = g_sq[b * NN + c];
    }
    if (tid < 64) qrow[tid] = xb[(size_t)q * 64 + tid];
    if (tid == 64) sqq_s = g_sq[b * NN + q];
    __syncthreads();
    {
        int r = tid >> 2, ch = tid & 3;
        int src = cidx[r];
        const float4* s4 = (const float4*)(xb + (size_t)src * 64);
#pragma unroll
        for (int u = 0; u < 4; u++) {
            float4 v = s4[ch * 4 + u];
            rows[r][ch * 16 + u * 4 + 0] = v.x;
            rows[r][ch * 16 + u * 4 + 1] = v.y;
            rows[r][ch * 16 + u * 4 + 2] = v.z;
            rows[r][ch * 16 + u * 4 + 3] = v.w;
        }
    }
    __syncthreads();

    if (tid < 32) {
        int lane = tid;
        float dot = 0.f;
#pragma unroll
        for (int c = 0; c < 64; c++)
            dot = __fmaf_rn(qrow[c], rows[lane][c], dot);
        float dist = __fmaf_rn(-2.f, dot, __fadd_rn(sqq_s, sqc[lane]));
        unsigned long long key =
            ((unsigned long long)mono_f(dist) << 32) | (unsigned)cidx[lane];
#pragma unroll
        for (int k = 2; k <= 32; k <<= 1) {
#pragma unroll
            for (int j = k >> 1; j > 0; j >>= 1) {
                unsigned long long o = __shfl_xor_sync(0xffffffffu, key, j);
                bool up = ((lane & k) == 0);
                bool keep_min = (((lane & j) == 0) == up);
                bool omin = o < key;
                key = (keep_min == omin) ? o : key;
            }
        }
        if (lane < 20)
            g_idx[((size_t)b * NN + q) * 20 + lane] = (int)(key & 0xFFFFFFFFull);
    }
}

// ---------------- edgeconv: mma.sync split-bf16 slotted GEMM ----------------
__global__ __launch_bounds__(256) void edgeconv_mma_kernel(const float* __restrict__ bias,
                                                           float* __restrict__ out) {
    __shared__ __align__(16) __nv_bfloat16 at[128][72];
    __shared__ __align__(16) __nv_bfloat16 wh[64][72];
    __shared__ __align__(16) __nv_bfloat16 wl[64][72];
    __shared__ int idxs[128 * 20];

    int tid = threadIdx.x, wid = tid >> 5, lane = tid & 31;
    int gid = lane >> 2, tig = lane & 3;
    int b = blockIdx.y, n0 = blockIdx.x * 128;
    const char* xhib = (const char*)g_xhi + (size_t)b * NN * 128;
    const char* xlob = (const char*)g_xlo + (size_t)b * NN * 128;

    for (int i = tid; i < 128 * 20; i += 256)
        idxs[i] = g_idx[((size_t)b * NN + n0 + i / 20) * 20 + (i % 20)];

    float acc[8][4];
#pragma unroll
    for (int j = 0; j < 8; j++)
#pragma unroll
        for (int k = 0; k < 4; k++) acc[j][k] = 0.f;

    int arow = wid * 16 + gid;

    for (int slot = 0; slot < 21; slot++) {
        __syncthreads();
#pragma unroll
        for (int i = 0; i < 2; i++) {
            int e = tid + 256 * i;
            int row = e >> 3, ch = e & 7;
            *(uint4*)&wh[row][ch * 8] =
                *(const uint4*)(g_wbh + slot * 4096 + row * 64 + ch * 8);
            *(uint4*)&wl[row][ch * 8] =
                *(const uint4*)(g_wbl + slot * 4096 + row * 64 + ch * 8);
        }
#pragma unroll
        for (int u = 0; u < 4; u++) {
            int i = tid + 256 * u;
            int row = i >> 3, k = i & 7;
            int src = slot ? idxs[row * 20 + slot - 1] : n0 + row;
            *(uint4*)&at[row][k * 8] = *(const uint4*)(xhib + (size_t)src * 128 + k * 16);
        }
        __syncthreads();
#pragma unroll
        for (int kk = 0; kk < 4; kk++) {
            uint32_t a0 = *(const uint32_t*)&at[arow][kk * 16 + tig * 2];
            uint32_t a1 = *(const uint32_t*)&at[arow + 8][kk * 16 + tig * 2];
            uint32_t a2 = *(const uint32_t*)&at[arow][kk * 16 + tig * 2 + 8];
            uint32_t a3 = *(const uint32_t*)&at[arow + 8][kk * 16 + tig * 2 + 8];
#pragma unroll
            for (int j = 0; j < 8; j++) {
                uint32_t b0 = *(const uint32_t*)&wh[j * 8 + gid][kk * 16 + tig * 2];
                uint32_t b1 = *(const uint32_t*)&wh[j * 8 + gid][kk * 16 + tig * 2 + 8];
                mma16816(acc[j], a0, a1, a2, a3, b0, b1);
            }
#pragma unroll
            for (int j = 0; j < 8; j++) {
                uint32_t b0 = *(const uint32_t*)&wl[j * 8 + gid][kk * 16 + tig * 2];
                uint32_t b1 = *(const uint32_t*)&wl[j * 8 + gid][kk * 16 + tig * 2 + 8];
                mma16816(acc[j], a0, a1, a2, a3, b0, b1);
            }
        }
        __syncthreads();
#pragma unroll
        for (int u = 0; u < 4; u++) {
            int i = tid + 256 * u;
            int row = i >> 3, k = i & 7;
            int src = slot ? idxs[row * 20 + slot - 1] : n0 + row;
            *(uint4*)&at[row][k * 8] = *(const uint4*)(xlob + (size_t)src * 128 + k * 16);
        }
        __syncthreads();
#pragma unroll
        for (int kk = 0; kk < 4; kk++) {
            uint32_t a0 = *(const uint32_t*)&at[arow][kk * 16 + tig * 2];
            uint32_t a1 = *(const uint32_t*)&at[arow + 8][kk * 16 + tig * 2];
            uint32_t a2 = *(const uint32_t*)&at[arow][kk * 16 + tig * 2 + 8];
            uint32_t a3 = *(const uint32_t*)&at[arow + 8][kk * 16 + tig * 2 + 8];
#pragma unroll
            for (int j = 0; j < 8; j++) {
                uint32_t b0 = *(const uint32_t*)&wh[j * 8 + gid][kk * 16 + tig * 2];
                uint32_t b1 = *(const uint32_t*)&wh[j * 8 + gid][kk * 16 + tig * 2 + 8];
                mma16816(acc[j], a0, a1, a2, a3, b0, b1);
            }
        }
    }

    float* ob = out + (size_t)b * OUTC * NN;
#pragma unroll
    for (int j = 0; j < 8; j++) {
        int o0 = j * 8 + tig * 2;
        float bv0 = __ldg(bias + o0);
        float bv1 = __ldg(bias + o0 + 1);
        ob[(size_t)o0 * NN + n0 + arow]           = acc[j][0] + bv0;
        ob[(size_t)(o0 + 1) * NN + n0 + arow]     = acc[j][1] + bv1;
        ob[(size_t)o0 * NN + n0 + arow + 8]       = acc[j][2] + bv0;
        ob[(size_t)(o0 + 1) * NN + n0 + arow + 8] = acc[j][3] + bv1;
    }
}

// ---------------- batchnorm: two-stage deterministic reduction ----------------
__global__ __launch_bounds__(256) void bn_part_kernel(const float* __restrict__ y) {
    int o = blockIdx.y, chunk = blockIdx.x;          // 32 chunks of 1024
    int tid = threadIdx.x;
    const float* p = y + ((size_t)(chunk >> 1) * OUTC + o) * NN + (chunk & 1) * 1024;
    float s = 0.f, ss = 0.f;
#pragma unroll
    for (int u = 0; u < 4; u++) {
        float v = p[tid + 256 * u];
        s += v;
        ss = fmaf(v, v, ss);
    }
#pragma unroll
    for (int off = 16; off; off >>= 1) {
        s  += __shfl_down_sync(0xffffffffu, s, off);
        ss += __shfl_down_sync(0xffffffffu, ss, off);
    }
    __shared__ float shs[8], shss[8];
    int w = tid >> 5;
    if ((tid & 31) == 0) { shs[w] = s; shss[w] = ss; }
    __syncthreads();
    if (tid == 0) {
        s = 0.f; ss = 0.f;
#pragma unroll
        for (int k = 0; k < 8; k++) { s += shs[k]; ss += shss[k]; }
        g_bps[o * 32 + chunk] = s;
        g_bpss[o * 32 + chunk] = ss;
    }
}

__global__ void bn_final_kernel(const float* __restrict__ gamma,
                                const float* __restrict__ beta) {
    int o = threadIdx.x;    // 64 threads
    float s = 0.f, ss = 0.f;
#pragma unroll
    for (int k = 0; k < 32; k++) {
        s += g_bps[o * 32 + k];
        ss += g_bpss[o * 32 + k];
    }
    float inv = 1.f / 32768.f;
    float mean = s * inv;
    float var = fmaf(ss, inv, -mean * mean);
    float r = rsqrtf(var + 1e-5f);
    float sc = gamma[o] * r;
    g_scale[o] = sc;
    g_shift[o] = beta[o] - mean * sc;
}

// ---------------- normalize + leaky relu ----------------
__global__ void bn_apply_kernel(float* __restrict__ y) {
    int i = blockIdx.x * 256 + threadIdx.x;
    int o = (i >> 11) & 63;
    float v = fmaf(y[i], g_scale[o], g_shift[o]);
    y[i] = v >= 0.f ? v : 0.2f * v;
}

// ---------------- launch ----------------
extern "C" void kernel_launch(void* const* d_in, const int* in_sizes, int n_in,
                              void* d_out, int out_size) {
    const float* x     = (const float*)d_in[0];  // (16, 64, 2048)
    const float* w     = (const float*)d_in[1];  // (64, 128, 20)
    const float* bias  = (const float*)d_in[2];  // (64,)
    const float* gamma = (const float*)d_in[3];  // (64,)
    const float* beta  = (const float*)d_in[4];  // (64,)
    float* out = (float*)d_out;                  // (16, 64, 2048)

    prep_xt_kernel<<<dim3(NN / 128, BB), 128>>>(x);
    sq_kernel<<<(BB * NN) / 256, 256>>>();
    prep_wb_kernel<<<dim3(21, 16), 256>>>(w);
    gram_kernel<<<dim3(NN / 128, NN / 128, BB), 128>>>();
    select_kernel<<<dim3(NN / 8, BB), 256>>>();
    rescue_kernel<<<dim3(NN, BB), 128>>>();
    edgeconv_mma_kernel<<<dim3(NN / 128, BB), 256>>>(bias, out);
    bn_part_kernel<<<dim3(32, OUTC), 256>>>(out);
    bn_final_kernel<<<1, OUTC>>>(gamma, beta);
    bn_apply_kernel<<<(BB * OUTC * NN) / 256, 256>>>(out);
}